// round 1
// baseline (speedup 1.0000x reference)
#include <cuda_runtime.h>
#include <cstdint>

// RationalsModel: out[i] = P(x[i]) / (|x[i] * Q(x[i])| + 1)
//   P = sum_{p=0}^{63} coef[p]      * x^p
//   Q = sum_{p=0}^{63} coef[64 + p] * x^p   (denominator = x * Q(x))
//
// Strategy: FMA-pipe-bound problem (~127 FMA/elem). Use Blackwell packed
// fma.rn.f32x2 (2 scalar FMAs per issue) with coefficients staged in shared
// memory pre-duplicated as f32x2 pairs. 8 elements per thread (4 packed lanes).

__device__ __forceinline__ uint64_t pack2(float lo, float hi) {
    uint64_t r;
    asm("mov.b64 %0, {%1, %2};" : "=l"(r) : "f"(lo), "f"(hi));
    return r;
}

__device__ __forceinline__ void unpack2(uint64_t v, float& lo, float& hi) {
    asm("mov.b64 {%0, %1}, %2;" : "=f"(lo), "=f"(hi) : "l"(v));
}

// d = a * b + c  (packed 2x f32)
__device__ __forceinline__ uint64_t fma2(uint64_t a, uint64_t b, uint64_t c) {
    uint64_t d;
    asm("fma.rn.f32x2 %0, %1, %2, %3;" : "=l"(d) : "l"(a), "l"(b), "l"(c));
    return d;
}

static constexpr int THREADS = 256;
static constexpr int ELEMS_PER_THREAD = 8;                 // 4 packed f32x2 lanes
static constexpr int ELEMS_PER_BLOCK = THREADS * ELEMS_PER_THREAD;  // 2048
static constexpr int F4_PER_BLOCK = ELEMS_PER_BLOCK / 4;            // 512

__global__ __launch_bounds__(THREADS)
void rational_kernel(const float4* __restrict__ x4,
                     const float* __restrict__ coef,
                     float4* __restrict__ out4)
{
    // Coefficients duplicated into both halves of an f32x2 pair so the
    // Horner step is a single ld.shared.b64 broadcast per polynomial.
    __shared__ uint64_t sN[64];
    __shared__ uint64_t sM[64];

    int tid = threadIdx.x;
    if (tid < 128) {
        uint32_t u = __float_as_uint(coef[tid]);
        uint64_t p = (uint64_t)u | ((uint64_t)u << 32);
        if (tid < 64) sN[tid] = p;
        else          sM[tid - 64] = p;
    }
    __syncthreads();

    // Two coalesced float4 loads per thread (stride THREADS between them).
    long base = (long)blockIdx.x * F4_PER_BLOCK + tid;
    float4 a = x4[base];
    float4 b = x4[base + THREADS];

    uint64_t xp[4];
    xp[0] = pack2(a.x, a.y);
    xp[1] = pack2(a.z, a.w);
    xp[2] = pack2(b.x, b.y);
    xp[3] = pack2(b.z, b.w);

    uint64_t accN[4], accD[4];
    {
        uint64_t n63 = sN[63];
        uint64_t m63 = sM[63];
#pragma unroll
        for (int j = 0; j < 4; j++) { accN[j] = n63; accD[j] = m63; }
    }

    // Fully unrolled dual Horner: 63 steps x (4 + 4) packed FMAs.
#pragma unroll
    for (int p = 62; p >= 0; p--) {
        uint64_t cn = sN[p];
        uint64_t cm = sM[p];
#pragma unroll
        for (int j = 0; j < 4; j++) {
            accN[j] = fma2(accN[j], xp[j], cn);
            accD[j] = fma2(accD[j], xp[j], cm);
        }
    }

    // Epilogue: den = x * Q(x); out = P / (|den| + 1).
    float4 o[2];
    float* of = reinterpret_cast<float*>(o);
#pragma unroll
    for (int j = 0; j < 4; j++) {
        float nlo, nhi, dlo, dhi, xlo, xhi;
        unpack2(accN[j], nlo, nhi);
        unpack2(accD[j], dlo, dhi);
        unpack2(xp[j],   xlo, xhi);
        float den_lo = fabsf(xlo * dlo) + 1.0f;
        float den_hi = fabsf(xhi * dhi) + 1.0f;
        of[2 * j]     = __fdividef(nlo, den_lo);
        of[2 * j + 1] = __fdividef(nhi, den_hi);
    }

    out4[base] = o[0];
    out4[base + THREADS] = o[1];
}

extern "C" void kernel_launch(void* const* d_in, const int* in_sizes, int n_in,
                              void* d_out, int out_size) {
    const float* x    = (const float*)d_in[0];
    const float* coef = (const float*)d_in[1];
    float* out        = (float*)d_out;

    int N = in_sizes[0];                 // 4194304, divisible by 2048
    int blocks = N / ELEMS_PER_BLOCK;

    rational_kernel<<<blocks, THREADS>>>(
        (const float4*)x, coef, (float4*)out);
}